// round 1
// baseline (speedup 1.0000x reference)
#include <cuda_runtime.h>
#include <cuda_bf16.h>

// Problem constants
#define NB 16
#define CI 64
#define CO 64
#define HH 128
#define WW 128
#define TH 16
#define TW 16
#define NTHREADS 256

// Dynamic smem layout (float offsets)
#define XS_OFF 0
#define XS_SZ (64*324)                 // x tile: [i][18*18], row stride 18
#define WS_OFF (XS_OFF + XS_SZ)        // 20736
#define WS_I_STRIDE 68                 // padded
#define WS_M_STRIDE (64*WS_I_STRIDE)
#define WS_SZ (4*WS_M_STRIDE)          // 17408
#define AS_OFF (WS_OFF + WS_SZ)        // 38144
#define AS_SZ (8*4*256)                // 8192: chunk A[j][m][pix]
#define CF_OFF (AS_OFF + AS_SZ)        // 46336
#define CF_SZ (4*256)
#define BS_OFF (CF_OFF + CF_SZ)        // 47360
#define SMEM_FLOATS (BS_OFF + 64)      // 47424
#define SMEM_BYTES (SMEM_FLOATS*4)     // 189696 bytes

__device__ __forceinline__ unsigned long long pack2(float lo, float hi) {
    unsigned long long r;
    asm("mov.b64 %0, {%1, %2};" : "=l"(r) : "f"(lo), "f"(hi));
    return r;
}
__device__ __forceinline__ void unpack2(unsigned long long v, float& lo, float& hi) {
    asm("mov.b64 {%0, %1}, %2;" : "=f"(lo), "=f"(hi) : "l"(v));
}
__device__ __forceinline__ void fma2(unsigned long long& d, unsigned long long a, unsigned long long b) {
    asm("fma.rn.f32x2 %0, %1, %2, %0;" : "+l"(d) : "l"(a), "l"(b));
}

__global__ __launch_bounds__(NTHREADS, 1)
void steered_kernel(const float* __restrict__ x, const float* __restrict__ theta,
                    const float* __restrict__ wts, const float* __restrict__ bias,
                    float* __restrict__ out) {
    extern __shared__ float sm[];
    const int tid = threadIdx.x;
    const int n  = blockIdx.z;
    const int h0 = blockIdx.y * TH;
    const int w0 = blockIdx.x * TW;

    // ---- Load x tile + halo (zero padded SAME boundary) ----
    {
        const float* xb = x + (size_t)n * CI * HH * WW;
        for (int e = tid; e < 64*324; e += NTHREADS) {
            int i   = e / 324;
            int rem = e - i*324;
            int r   = rem / 18;
            int c   = rem - r*18;
            int gh = h0 - 1 + r;
            int gw = w0 - 1 + c;
            float v = 0.f;
            if (gh >= 0 && gh < HH && gw >= 0 && gw < WW)
                v = xb[(i*HH + gh)*WW + gw];
            sm[XS_OFF + e] = v;
        }
    }
    // ---- weights (O,I,4) -> Ws[m][i][o] ----
    for (int e = tid; e < CO*CI*4; e += NTHREADS) {
        int o = e >> 8;
        int i = (e >> 2) & 63;
        int m = e & 3;
        sm[WS_OFF + m*WS_M_STRIDE + i*WS_I_STRIDE + o] = wts[e];
    }
    if (tid < CO) sm[BS_OFF + tid] = bias[tid];
    // ---- per-pixel harmonic coefficients ----
    {
        int py = tid >> 4, px = tid & 15;
        float th = theta[((size_t)n*HH + (h0+py))*WW + (w0+px)];
        float a = 6.28318530717958647692f * th;
        float s1v, c1v;
        sincosf(a, &s1v, &c1v);
        sm[CF_OFF + 0*256 + tid] = c1v;
        sm[CF_OFF + 1*256 + tid] = s1v;
        sm[CF_OFF + 2*256 + tid] = 2.f*c1v*c1v - 1.f;
        sm[CF_OFF + 3*256 + tid] = 2.f*s1v*c1v;
    }
    __syncthreads();

    const int lane = tid & 31;
    const int warp = tid >> 5;
    const int o0 = warp * 8;
    const int pA = lane * 4;
    const int pB = 128 + lane * 4;

    const float c1 = sm[CF_OFF + tid];
    const float s1 = sm[CF_OFF + 256 + tid];
    const float c2 = sm[CF_OFF + 512 + tid];
    const float s2 = sm[CF_OFF + 768 + tid];
    const float cps = c1 + s1, cms = c1 - s1;
    const int py = tid >> 4, px = tid & 15;
    const int ctr = (py+1)*18 + (px+1);

    unsigned long long acc[8][4];
    #pragma unroll
    for (int a_ = 0; a_ < 8; a_++)
        #pragma unroll
        for (int b_ = 0; b_ < 4; b_++) acc[a_][b_] = 0ull;

    const float Q = 0.35355339059327376220f;  // 1/(2*sqrt(2)): ring value & k=1 corner basis

    for (int ch = 0; ch < 8; ch++) {
        const int ic0 = ch * 8;
        // ---- build A chunk: A[j][m][pix] for i = ic0..ic0+7 ----
        #pragma unroll
        for (int j = 0; j < 8; j++) {
            const float* xp = sm + XS_OFF + (ic0 + j)*324 + ctr;
            float t0 = xp[-19], t1 = xp[-18], t2 = xp[-17];
            float t3 = xp[-1],  t4 = xp[0],   t5 = xp[1];
            float t6 = xp[17],  t7 = xp[18],  t8 = xp[19];
            float ring = ((t0+t1)+(t2+t3)) + ((t5+t6)+(t7+t8));
            float d80 = t8 - t0, d26 = t2 - t6;
            float d53 = t5 - t3, d71 = t7 - t1;
            float z2 = Q*(cps*d80 + cms*d26) + 0.5f*(c1*d53 + s1*d71);
            float s0826 = (t0+t8) - (t2+t6);
            float s3517 = (t3+t5) - (t1+t7);
            float z3 = 0.5f*(s2*s0826 + c2*s3517);
            float* Ap = sm + AS_OFF + j*(4*256);
            Ap[0*256 + tid] = t4;        // m=0: center delta
            Ap[1*256 + tid] = Q * ring;  // m=1: ring
            Ap[2*256 + tid] = z2;        // m=2: k=1 steered
            Ap[3*256 + tid] = z3;        // m=3: k=2 steered
        }
        __syncthreads();
        // ---- GEMM over the 32 k-values in this chunk ----
        #pragma unroll
        for (int j = 0; j < 8; j++) {
            const float* Wj = sm + WS_OFF + (ic0 + j)*WS_I_STRIDE + o0;
            #pragma unroll
            for (int m = 0; m < 4; m++) {
                const float* Ap = sm + AS_OFF + (j*4 + m)*256;
                ulonglong2 aA = *(const ulonglong2*)(Ap + pA);
                ulonglong2 aB = *(const ulonglong2*)(Ap + pB);
                const float* W = Wj + m*WS_M_STRIDE;
                float4 wa = *(const float4*)(W);
                float4 wb = *(const float4*)(W + 4);
                unsigned long long wd;
#define MMA_O(oo, wv) \
                wd = pack2((wv), (wv)); \
                fma2(acc[oo][0], aA.x, wd); fma2(acc[oo][1], aA.y, wd); \
                fma2(acc[oo][2], aB.x, wd); fma2(acc[oo][3], aB.y, wd);
                MMA_O(0, wa.x) MMA_O(1, wa.y) MMA_O(2, wa.z) MMA_O(3, wa.w)
                MMA_O(4, wb.x) MMA_O(5, wb.y) MMA_O(6, wb.z) MMA_O(7, wb.w)
#undef MMA_O
            }
        }
        __syncthreads();
    }

    // ---- epilogue: add bias, store ----
    #pragma unroll
    for (int oo = 0; oo < 8; oo++) {
        int o = o0 + oo;
        float b = sm[BS_OFF + o];
        {
            int p = pA;
            int pyq = p >> 4, pxq = p & 15;
            float lo, hi;
            float4 r;
            unpack2(acc[oo][0], lo, hi); r.x = lo + b; r.y = hi + b;
            unpack2(acc[oo][1], lo, hi); r.z = lo + b; r.w = hi + b;
            *(float4*)(out + (((size_t)n*CO + o)*HH + (h0+pyq))*WW + (w0+pxq)) = r;
        }
        {
            int p = pB;
            int pyq = p >> 4, pxq = p & 15;
            float lo, hi;
            float4 r;
            unpack2(acc[oo][2], lo, hi); r.x = lo + b; r.y = hi + b;
            unpack2(acc[oo][3], lo, hi); r.z = lo + b; r.w = hi + b;
            *(float4*)(out + (((size_t)n*CO + o)*HH + (h0+pyq))*WW + (w0+pxq)) = r;
        }
    }
}

extern "C" void kernel_launch(void* const* d_in, const int* in_sizes, int n_in,
                              void* d_out, int out_size) {
    const float* x     = (const float*)d_in[0];
    const float* theta = (const float*)d_in[1];
    const float* wts   = (const float*)d_in[2];
    const float* bias  = (const float*)d_in[3];
    float* out = (float*)d_out;

    cudaFuncSetAttribute(steered_kernel,
                         cudaFuncAttributeMaxDynamicSharedMemorySize, SMEM_BYTES);
    dim3 grid(WW/TW, HH/TH, NB);
    steered_kernel<<<grid, NTHREADS, SMEM_BYTES>>>(x, theta, wts, bias, out);
}

// round 2
// speedup vs baseline: 1.4608x; 1.4608x over previous
#include <cuda_runtime.h>

// Problem constants
#define NB 16
#define CI 64
#define CO 64
#define HH 128
#define WW 128
#define TH 16
#define TW 16
#define NTHREADS 256

// x chunking
#define XCH 8                      // channels per prefetched x chunk
#define XS_CH 324                  // 18*18 per channel
#define XS_CHUNK (XCH*XS_CH)       // 2592 floats
// smem layout (float offsets)
#define XS_OFF 0
#define XS_SZ (2*XS_CHUNK)         // 5184 (double buffered)
#define WS_OFF XS_SZ
#define WS_I_STRIDE 68             // padded (16B-aligned float4 rows, reduced STS conflicts)
#define WS_M_STRIDE (64*WS_I_STRIDE)
#define WS_SZ (4*WS_M_STRIDE)      // 17408
#define AS_OFF (WS_OFF+WS_SZ)      // 22592
#define AS_SZ (4*4*256)            // 4096: A[j<4][m<4][256 pix]
#define SMEM_FLOATS (AS_OFF+AS_SZ) // 26688
#define SMEM_BYTES (SMEM_FLOATS*4) // 106752 B -> 2 CTAs/SM

__device__ __forceinline__ unsigned long long pack2(float lo, float hi) {
    unsigned long long r;
    asm("mov.b64 %0, {%1, %2};" : "=l"(r) : "f"(lo), "f"(hi));
    return r;
}
__device__ __forceinline__ void unpack2(unsigned long long v, float& lo, float& hi) {
    asm("mov.b64 {%0, %1}, %2;" : "=f"(lo), "=f"(hi) : "l"(v));
}
__device__ __forceinline__ void fma2(unsigned long long& d, unsigned long long a, unsigned long long b) {
    asm("fma.rn.f32x2 %0, %1, %2, %0;" : "+l"(d) : "l"(a), "l"(b));
}

__device__ __forceinline__ void load_chunk_async(const float* __restrict__ xb, int ch, int buf,
                                                 int h0, int w0, int tid, unsigned dbase0) {
    const int ic0 = ch * XCH;
    unsigned dbase = dbase0 + (unsigned)(buf * XS_CHUNK) * 4u;
    #pragma unroll 3
    for (int e = tid; e < XS_CHUNK; e += NTHREADS) {
        int j   = e / XS_CH;
        int rem = e - j * XS_CH;
        int r   = rem / 18;
        int c   = rem - r * 18;
        int gh = h0 - 1 + r, gw = w0 - 1 + c;
        bool v = ((unsigned)gh < (unsigned)HH) && ((unsigned)gw < (unsigned)WW);
        const float* src = v ? (xb + ((size_t)(ic0 + j) * HH + gh) * WW + gw) : xb;
        int sz = v ? 4 : 0;
        asm volatile("cp.async.ca.shared.global [%0], [%1], 4, %2;"
                     :: "r"(dbase + (unsigned)e * 4u), "l"(src), "r"(sz));
    }
}

__global__ __launch_bounds__(NTHREADS, 2)
void steered_kernel(const float* __restrict__ x, const float* __restrict__ theta,
                    const float* __restrict__ wts, const float* __restrict__ bias,
                    float* __restrict__ out) {
    extern __shared__ float sm[];
    const unsigned smem_u32 = (unsigned)__cvta_generic_to_shared(sm);
    const int tid = threadIdx.x;
    const int n  = blockIdx.z;
    const int h0 = blockIdx.y * TH;
    const int w0 = blockIdx.x * TW;
    const float* xb = x + (size_t)n * CI * HH * WW;

    // ---- prefetch x chunks 0 and 1 ----
    load_chunk_async(xb, 0, 0, h0, w0, tid, smem_u32);
    asm volatile("cp.async.commit_group;" ::: "memory");
    load_chunk_async(xb, 1, 1, h0, w0, tid, smem_u32);
    asm volatile("cp.async.commit_group;" ::: "memory");

    // ---- weights (O,I,4) -> Ws[m][i][o] (overlaps cp.async) ----
    for (int e = tid; e < CO * CI; e += NTHREADS) {
        float4 v = ((const float4*)wts)[e];      // wts[o][i][0..3]
        int o = e >> 6, i = e & 63;
        float* p = sm + WS_OFF + i * WS_I_STRIDE + o;
        p[0]               = v.x;
        p[WS_M_STRIDE]     = v.y;
        p[2*WS_M_STRIDE]   = v.z;
        p[3*WS_M_STRIDE]   = v.w;
    }

    // ---- per-pixel harmonic coefficients (registers only) ----
    const int py = tid >> 4, px = tid & 15;
    float th = theta[((size_t)n * HH + (h0 + py)) * WW + (w0 + px)];
    float aang = 6.28318530717958647692f * th;
    float s1, c1;
    sincosf(aang, &s1, &c1);
    const float c2 = 2.f * c1 * c1 - 1.f;
    const float s2 = 2.f * s1 * c1;
    const float cps = c1 + s1, cms = c1 - s1;
    const int ctr = (py + 1) * 18 + (px + 1);

    const int lane = tid & 31;
    const int warp = tid >> 5;
    const int o0 = warp * 8;
    const int pA = lane * 4;
    const int pB = 128 + lane * 4;

    unsigned long long acc[8][4];
    #pragma unroll
    for (int a_ = 0; a_ < 8; a_++)
        #pragma unroll
        for (int b_ = 0; b_ < 4; b_++) acc[a_][b_] = 0ull;

    const float Q = 0.35355339059327376220f;  // 1/(2*sqrt(2))

    asm volatile("cp.async.wait_group 1;" ::: "memory");  // chunk 0 ready
    __syncthreads();

    for (int ch = 0; ch < 8; ch++) {
        const float* xsb = sm + XS_OFF + (ch & 1) * XS_CHUNK;
        #pragma unroll 1
        for (int sub = 0; sub < 2; sub++) {
            // ---- build A: 4 channels, per-pixel steered taps ----
            #pragma unroll
            for (int j = 0; j < 4; j++) {
                const float* xp = xsb + (sub * 4 + j) * XS_CH + ctr;
                float t0 = xp[-19], t1 = xp[-18], t2 = xp[-17];
                float t3 = xp[-1],  t4 = xp[0],   t5 = xp[1];
                float t6 = xp[17],  t7 = xp[18],  t8 = xp[19];
                float ring = ((t0 + t1) + (t2 + t3)) + ((t5 + t6) + (t7 + t8));
                float d80 = t8 - t0, d26 = t2 - t6;
                float d53 = t5 - t3, d71 = t7 - t1;
                float z2 = Q * (cps * d80 + cms * d26) + 0.5f * (c1 * d53 + s1 * d71);
                float s0826 = (t0 + t8) - (t2 + t6);
                float s3517 = (t3 + t5) - (t1 + t7);
                float z3 = 0.5f * (s2 * s0826 + c2 * s3517);
                float* Ap = sm + AS_OFF + j * 1024;
                Ap[tid]        = t4;        // m=0 center
                Ap[256 + tid]  = Q * ring;  // m=1 ring
                Ap[512 + tid]  = z2;        // m=2 k=1 steered
                Ap[768 + tid]  = z3;        // m=3 k=2 steered
            }
            __syncthreads();
            // after sub==1's barrier every thread is done reading XS[buf]:
            // prefetch chunk ch+2 into this buffer while GEMM runs
            if (sub == 1 && ch < 6) {
                load_chunk_async(xb, ch + 2, ch & 1, h0, w0, tid, smem_u32);
                asm volatile("cp.async.commit_group;" ::: "memory");
            }
            // ---- GEMM over 16 k-values (4 ch x 4 m) ----
            const int ic0 = ch * 8 + sub * 4;
            #pragma unroll
            for (int j = 0; j < 4; j++) {
                const float* Wj = sm + WS_OFF + (ic0 + j) * WS_I_STRIDE + o0;
                #pragma unroll
                for (int m = 0; m < 4; m++) {
                    const float* Ap = sm + AS_OFF + (j * 4 + m) * 256;
                    ulonglong2 aA = *(const ulonglong2*)(Ap + pA);
                    ulonglong2 aB = *(const ulonglong2*)(Ap + pB);
                    const float* W = Wj + m * WS_M_STRIDE;
                    float4 wa = *(const float4*)(W);
                    float4 wb = *(const float4*)(W + 4);
                    unsigned long long wd;
#define MMA_O(oo, wv) \
                    wd = pack2((wv), (wv)); \
                    fma2(acc[oo][0], aA.x, wd); fma2(acc[oo][1], aA.y, wd); \
                    fma2(acc[oo][2], aB.x, wd); fma2(acc[oo][3], aB.y, wd);
                    MMA_O(0, wa.x) MMA_O(1, wa.y) MMA_O(2, wa.z) MMA_O(3, wa.w)
                    MMA_O(4, wb.x) MMA_O(5, wb.y) MMA_O(6, wb.z) MMA_O(7, wb.w)
#undef MMA_O
                }
            }
            if (sub == 1) {
                if (ch < 6) { asm volatile("cp.async.wait_group 1;" ::: "memory"); }
                else        { asm volatile("cp.async.wait_group 0;" ::: "memory"); }
            }
            __syncthreads();
        }
    }

    // ---- epilogue: bias + store ----
    #pragma unroll
    for (int oo = 0; oo < 8; oo++) {
        int o = o0 + oo;
        float b = __ldg(bias + o);
        {
            int p = pA;
            int pyq = p >> 4, pxq = p & 15;
            float lo, hi; float4 r;
            unpack2(acc[oo][0], lo, hi); r.x = lo + b; r.y = hi + b;
            unpack2(acc[oo][1], lo, hi); r.z = lo + b; r.w = hi + b;
            *(float4*)(out + (((size_t)n * CO + o) * HH + (h0 + pyq)) * WW + (w0 + pxq)) = r;
        }
        {
            int p = pB;
            int pyq = p >> 4, pxq = p & 15;
            float lo, hi; float4 r;
            unpack2(acc[oo][2], lo, hi); r.x = lo + b; r.y = hi + b;
            unpack2(acc[oo][3], lo, hi); r.z = lo + b; r.w = hi + b;
            *(float4*)(out + (((size_t)n * CO + o) * HH + (h0 + pyq)) * WW + (w0 + pxq)) = r;
        }
    }
}

extern "C" void kernel_launch(void* const* d_in, const int* in_sizes, int n_in,
                              void* d_out, int out_size) {
    const float* x     = (const float*)d_in[0];
    const float* theta = (const float*)d_in[1];
    const float* wts   = (const float*)d_in[2];
    const float* bias  = (const float*)d_in[3];
    float* out = (float*)d_out;

    cudaFuncSetAttribute(steered_kernel,
                         cudaFuncAttributeMaxDynamicSharedMemorySize, SMEM_BYTES);
    dim3 grid(WW / TW, HH / TH, NB);
    steered_kernel<<<grid, NTHREADS, SMEM_BYTES>>>(x, theta, wts, bias, out);
}

// round 3
// speedup vs baseline: 1.4610x; 1.0001x over previous
#include <cuda_runtime.h>

// Problem constants
#define NB 16
#define CI 64
#define CO 64
#define HH 128
#define WW 128
#define TH 16
#define TW 16
#define NTHREADS 256

// x chunking
#define XCH 8                      // channels per prefetched x chunk
#define XS_CH 324                  // 18*18 per channel
#define XS_CHUNK (XCH*XS_CH)       // 2592 floats
// smem layout (float offsets)
#define XS_OFF 0
#define XS_SZ (2*XS_CHUNK)         // 5184 (double buffered)
#define WS_OFF XS_SZ
#define WS_I_STRIDE 68             // padded (16B-aligned float4 rows, reduced STS conflicts)
#define WS_M_STRIDE (64*WS_I_STRIDE)
#define WS_SZ (4*WS_M_STRIDE)      // 17408
#define AS_OFF (WS_OFF+WS_SZ)      // 22592
#define AS_SZ (4*4*256)            // 4096: A[j<4][m<4][256 pix]
#define SMEM_FLOATS (AS_OFF+AS_SZ) // 26688
#define SMEM_BYTES (SMEM_FLOATS*4) // 106752 B -> 2 CTAs/SM

__device__ __forceinline__ unsigned long long pack2(float lo, float hi) {
    unsigned long long r;
    asm("mov.b64 %0, {%1, %2};" : "=l"(r) : "f"(lo), "f"(hi));
    return r;
}
__device__ __forceinline__ void unpack2(unsigned long long v, float& lo, float& hi) {
    asm("mov.b64 {%0, %1}, %2;" : "=f"(lo), "=f"(hi) : "l"(v));
}
__device__ __forceinline__ void fma2(unsigned long long& d, unsigned long long a, unsigned long long b) {
    asm("fma.rn.f32x2 %0, %1, %2, %0;" : "+l"(d) : "l"(a), "l"(b));
}

__device__ __forceinline__ void load_chunk_async(const float* __restrict__ xb, int ch, int buf,
                                                 int h0, int w0, int tid, unsigned dbase0) {
    const int ic0 = ch * XCH;
    unsigned dbase = dbase0 + (unsigned)(buf * XS_CHUNK) * 4u;
    #pragma unroll 3
    for (int e = tid; e < XS_CHUNK; e += NTHREADS) {
        int j   = e / XS_CH;
        int rem = e - j * XS_CH;
        int r   = rem / 18;
        int c   = rem - r * 18;
        int gh = h0 - 1 + r, gw = w0 - 1 + c;
        bool v = ((unsigned)gh < (unsigned)HH) && ((unsigned)gw < (unsigned)WW);
        const float* src = v ? (xb + ((size_t)(ic0 + j) * HH + gh) * WW + gw) : xb;
        int sz = v ? 4 : 0;
        asm volatile("cp.async.ca.shared.global [%0], [%1], 4, %2;"
                     :: "r"(dbase + (unsigned)e * 4u), "l"(src), "r"(sz));
    }
}

__global__ __launch_bounds__(NTHREADS, 2)
void steered_kernel(const float* __restrict__ x, const float* __restrict__ theta,
                    const float* __restrict__ wts, const float* __restrict__ bias,
                    float* __restrict__ out) {
    extern __shared__ float sm[];
    const unsigned smem_u32 = (unsigned)__cvta_generic_to_shared(sm);
    const int tid = threadIdx.x;
    const int n  = blockIdx.z;
    const int h0 = blockIdx.y * TH;
    const int w0 = blockIdx.x * TW;
    const float* xb = x + (size_t)n * CI * HH * WW;

    // ---- prefetch x chunks 0 and 1 ----
    load_chunk_async(xb, 0, 0, h0, w0, tid, smem_u32);
    asm volatile("cp.async.commit_group;" ::: "memory");
    load_chunk_async(xb, 1, 1, h0, w0, tid, smem_u32);
    asm volatile("cp.async.commit_group;" ::: "memory");

    // ---- weights (O,I,4) -> Ws[m][i][o] (overlaps cp.async) ----
    for (int e = tid; e < CO * CI; e += NTHREADS) {
        float4 v = ((const float4*)wts)[e];      // wts[o][i][0..3]
        int o = e >> 6, i = e & 63;
        float* p = sm + WS_OFF + i * WS_I_STRIDE + o;
        p[0]               = v.x;
        p[WS_M_STRIDE]     = v.y;
        p[2*WS_M_STRIDE]   = v.z;
        p[3*WS_M_STRIDE]   = v.w;
    }

    // ---- per-pixel harmonic coefficients (registers only) ----
    const int py = tid >> 4, px = tid & 15;
    float th = theta[((size_t)n * HH + (h0 + py)) * WW + (w0 + px)];
    float aang = 6.28318530717958647692f * th;
    float s1, c1;
    sincosf(aang, &s1, &c1);
    const float c2 = 2.f * c1 * c1 - 1.f;
    const float s2 = 2.f * s1 * c1;
    const float cps = c1 + s1, cms = c1 - s1;
    const int ctr = (py + 1) * 18 + (px + 1);

    const int lane = tid & 31;
    const int warp = tid >> 5;
    const int o0 = warp * 8;
    const int pA = lane * 4;
    const int pB = 128 + lane * 4;

    unsigned long long acc[8][4];
    #pragma unroll
    for (int a_ = 0; a_ < 8; a_++)
        #pragma unroll
        for (int b_ = 0; b_ < 4; b_++) acc[a_][b_] = 0ull;

    const float Q = 0.35355339059327376220f;  // 1/(2*sqrt(2))

    asm volatile("cp.async.wait_group 1;" ::: "memory");  // chunk 0 ready
    __syncthreads();

    for (int ch = 0; ch < 8; ch++) {
        const float* xsb = sm + XS_OFF + (ch & 1) * XS_CHUNK;
        #pragma unroll 1
        for (int sub = 0; sub < 2; sub++) {
            // ---- build A: 4 channels, per-pixel steered taps ----
            #pragma unroll
            for (int j = 0; j < 4; j++) {
                const float* xp = xsb + (sub * 4 + j) * XS_CH + ctr;
                float t0 = xp[-19], t1 = xp[-18], t2 = xp[-17];
                float t3 = xp[-1],  t4 = xp[0],   t5 = xp[1];
                float t6 = xp[17],  t7 = xp[18],  t8 = xp[19];
                float ring = ((t0 + t1) + (t2 + t3)) + ((t5 + t6) + (t7 + t8));
                float d80 = t8 - t0, d26 = t2 - t6;
                float d53 = t5 - t3, d71 = t7 - t1;
                float z2 = Q * (cps * d80 + cms * d26) + 0.5f * (c1 * d53 + s1 * d71);
                float s0826 = (t0 + t8) - (t2 + t6);
                float s3517 = (t3 + t5) - (t1 + t7);
                float z3 = 0.5f * (s2 * s0826 + c2 * s3517);
                float* Ap = sm + AS_OFF + j * 1024;
                Ap[tid]        = t4;        // m=0 center
                Ap[256 + tid]  = Q * ring;  // m=1 ring
                Ap[512 + tid]  = z2;        // m=2 k=1 steered
                Ap[768 + tid]  = z3;        // m=3 k=2 steered
            }
            __syncthreads();
            // after sub==1's barrier every thread is done reading XS[buf]:
            // prefetch chunk ch+2 into this buffer while GEMM runs
            if (sub == 1 && ch < 6) {
                load_chunk_async(xb, ch + 2, ch & 1, h0, w0, tid, smem_u32);
                asm volatile("cp.async.commit_group;" ::: "memory");
            }
            // ---- GEMM over 16 k-values (4 ch x 4 m) ----
            const int ic0 = ch * 8 + sub * 4;
            #pragma unroll
            for (int j = 0; j < 4; j++) {
                const float* Wj = sm + WS_OFF + (ic0 + j) * WS_I_STRIDE + o0;
                #pragma unroll
                for (int m = 0; m < 4; m++) {
                    const float* Ap = sm + AS_OFF + (j * 4 + m) * 256;
                    ulonglong2 aA = *(const ulonglong2*)(Ap + pA);
                    ulonglong2 aB = *(const ulonglong2*)(Ap + pB);
                    const float* W = Wj + m * WS_M_STRIDE;
                    float4 wa = *(const float4*)(W);
                    float4 wb = *(const float4*)(W + 4);
                    unsigned long long wd;
#define MMA_O(oo, wv) \
                    wd = pack2((wv), (wv)); \
                    fma2(acc[oo][0], aA.x, wd); fma2(acc[oo][1], aA.y, wd); \
                    fma2(acc[oo][2], aB.x, wd); fma2(acc[oo][3], aB.y, wd);
                    MMA_O(0, wa.x) MMA_O(1, wa.y) MMA_O(2, wa.z) MMA_O(3, wa.w)
                    MMA_O(4, wb.x) MMA_O(5, wb.y) MMA_O(6, wb.z) MMA_O(7, wb.w)
#undef MMA_O
                }
            }
            if (sub == 1) {
                if (ch < 6) { asm volatile("cp.async.wait_group 1;" ::: "memory"); }
                else        { asm volatile("cp.async.wait_group 0;" ::: "memory"); }
            }
            __syncthreads();
        }
    }

    // ---- epilogue: bias + store ----
    #pragma unroll
    for (int oo = 0; oo < 8; oo++) {
        int o = o0 + oo;
        float b = __ldg(bias + o);
        {
            int p = pA;
            int pyq = p >> 4, pxq = p & 15;
            float lo, hi; float4 r;
            unpack2(acc[oo][0], lo, hi); r.x = lo + b; r.y = hi + b;
            unpack2(acc[oo][1], lo, hi); r.z = lo + b; r.w = hi + b;
            *(float4*)(out + (((size_t)n * CO + o) * HH + (h0 + pyq)) * WW + (w0 + pxq)) = r;
        }
        {
            int p = pB;
            int pyq = p >> 4, pxq = p & 15;
            float lo, hi; float4 r;
            unpack2(acc[oo][2], lo, hi); r.x = lo + b; r.y = hi + b;
            unpack2(acc[oo][3], lo, hi); r.z = lo + b; r.w = hi + b;
            *(float4*)(out + (((size_t)n * CO + o) * HH + (h0 + pyq)) * WW + (w0 + pxq)) = r;
        }
    }
}

extern "C" void kernel_launch(void* const* d_in, const int* in_sizes, int n_in,
                              void* d_out, int out_size) {
    const float* x     = (const float*)d_in[0];
    const float* theta = (const float*)d_in[1];
    const float* wts   = (const float*)d_in[2];
    const float* bias  = (const float*)d_in[3];
    float* out = (float*)d_out;

    cudaFuncSetAttribute(steered_kernel,
                         cudaFuncAttributeMaxDynamicSharedMemorySize, SMEM_BYTES);
    dim3 grid(WW / TW, HH / TH, NB);
    steered_kernel<<<grid, NTHREADS, SMEM_BYTES>>>(x, theta, wts, bias, out);
}